// round 16
// baseline (speedup 1.0000x reference)
#include <cuda_runtime.h>
#include <cuda_fp16.h>
#include <cstdint>
#include <cstddef>

// ---------------- problem constants ----------------
#define B_   256
#define T_   361
#define C_   512
#define H_   8
#define DH_  64
#define MLP_ 2048
#define M_   (B_ * T_)          // 92416 = 722*128
#define SPAN_ 37
#define TABLE_ 1369
#define BSTR_ 384               // padded bias row stride
#define QKV_ 1536               // packed QKV row stride

// ---------------- PTX helpers (baseline features only) ----------------
__device__ __forceinline__ uint32_t smem_u32(const void* p) {
  uint32_t a;
  asm("{ .reg .u64 t; cvta.to.shared.u64 t, %1; cvt.u32.u64 %0, t; }" : "=r"(a) : "l"(p));
  return a;
}
__device__ __forceinline__ void cpa16(uint32_t s, const void* g) {
  asm volatile("cp.async.cg.shared.global [%0], [%1], 16;" :: "r"(s), "l"(g));
}
__device__ __forceinline__ void cpa16z(uint32_t s, const void* g, bool v) {
  int sz = v ? 16 : 0;
  asm volatile("cp.async.cg.shared.global [%0], [%1], 16, %2;" :: "r"(s), "l"(g), "r"(sz));
}
#define CP_COMMIT() asm volatile("cp.async.commit_group;" ::: "memory")
template<int Nw> __device__ __forceinline__ void cp_wait() {
  asm volatile("cp.async.wait_group %0;" :: "n"(Nw) : "memory");
}
__device__ __forceinline__ void ldsm4(uint32_t* r, uint32_t a) {
  asm volatile("ldmatrix.sync.aligned.m8n8.x4.shared.b16 {%0,%1,%2,%3}, [%4];"
               : "=r"(r[0]), "=r"(r[1]), "=r"(r[2]), "=r"(r[3]) : "r"(a));
}
__device__ __forceinline__ void ldsm4t(uint32_t* r, uint32_t a) {
  asm volatile("ldmatrix.sync.aligned.m8n8.x4.trans.shared.b16 {%0,%1,%2,%3}, [%4];"
               : "=r"(r[0]), "=r"(r[1]), "=r"(r[2]), "=r"(r[3]) : "r"(a));
}
__device__ __forceinline__ void mma16816(float* c, const uint32_t* a,
                                         uint32_t b0, uint32_t b1) {
  asm volatile(
      "mma.sync.aligned.m16n8k16.row.col.f32.f16.f16.f32 "
      "{%0,%1,%2,%3}, {%4,%5,%6,%7}, {%8,%9}, {%0,%1,%2,%3};"
      : "+f"(c[0]), "+f"(c[1]), "+f"(c[2]), "+f"(c[3])
      : "r"(a[0]), "r"(a[1]), "r"(a[2]), "r"(a[3]), "r"(b0), "r"(b1));
}

// ---------------- scratch (static device globals) ----------------
__device__ __half g_Y   [(size_t)M_ * C_];
__device__ __half g_QKV [(size_t)M_ * QKV_ + 64 * QKV_];
__device__ __half g_CX  [(size_t)M_ * C_];
__device__ float  g_X1  [(size_t)M_ * C_];
__device__ __half g_HI  [(size_t)M_ * MLP_];
__device__ float  g_BIAS[(size_t)H_ * T_ * BSTR_ + 16];
__device__ float  g_BQKV[QKV_];
#define WOFF_Q  0
#define WOFF_K  (512 * 512)
#define WOFF_V  (2 * 512 * 512)
#define WOFF_O  (3 * 512 * 512)
#define WOFF_1  (4 * 512 * 512)
#define WOFF_2  (4 * 512 * 512 + 2048 * 512)
#define WTOT    (4 * 512 * 512 + 2 * 2048 * 512)
__device__ __half g_W[WTOT];           // single-fp16 transposed weights [N,K]

// ---------------- helpers ----------------
__device__ __forceinline__ void pksplit(float p0, float p1, uint32_t& hi, uint32_t& lo) {
  __half2 h = __floats2half2_rn(p0, p1);
  float r0 = p0 - __half2float(__low2half(h));
  float r1 = p1 - __half2float(__high2half(h));
  __half2 l = __floats2half2_rn(r0, r1);
  hi = *(uint32_t*)&h; lo = *(uint32_t*)&l;
}
__device__ __forceinline__ uint32_t pk2h(float a, float b) {
  __half2 h = __floats2half2_rn(a, b);
  return *(uint32_t*)&h;
}
__device__ __forceinline__ float gelu_f(float x) {
  float x3 = x * x * x;
  float t = tanhf(0.7978845608028654f * fmaf(0.044715f, x3, x));
  return 0.5f * x * (1.0f + t);
}

// ---------------- weight prep (all 6 weights, one launch, single fp16) ----------------
__global__ __launch_bounds__(256) void wprep_all(
    const float* __restrict__ Wq, const float* __restrict__ Wk,
    const float* __restrict__ Wv, const float* __restrict__ Wo,
    const float* __restrict__ W1, const float* __restrict__ W2,
    __half* __restrict__ wout) {
  int z = blockIdx.z;
  const float* W; int K, N; size_t off;
  switch (z) {
    case 0: W = Wq; K = 512;  N = 512;  off = WOFF_Q; break;
    case 1: W = Wk; K = 512;  N = 512;  off = WOFF_K; break;
    case 2: W = Wv; K = 512;  N = 512;  off = WOFF_V; break;
    case 3: W = Wo; K = 512;  N = 512;  off = WOFF_O; break;
    case 4: W = W1; K = 512;  N = 2048; off = WOFF_1; break;
    default:W = W2; K = 2048; N = 512;  off = WOFF_2; break;
  }
  int n0 = blockIdx.x * 32, k0 = blockIdx.y * 32;
  if (n0 >= N || k0 >= K) return;
  __half* wo = wout + off;
  __shared__ float ts[32][33];
  int tr = threadIdx.x >> 5, tc = threadIdx.x & 31;
  #pragma unroll
  for (int i = 0; i < 4; i++) {
    int r = tr + i * 8;
    ts[r][tc] = W[(size_t)(k0 + r) * N + n0 + tc];
  }
  __syncthreads();
  #pragma unroll
  for (int i = 0; i < 4; i++) {
    int r = tr + i * 8;
    wo[(size_t)(n0 + r) * K + k0 + tc] = __float2half_rn(ts[tc][r]);
  }
}

// ---------------- bias expansion + QKV bias concat ----------------
__global__ void setup_bias(const float* __restrict__ rpb, float* __restrict__ bias,
                           const float* __restrict__ bq, const float* __restrict__ bk,
                           const float* __restrict__ bv, float* __restrict__ bqkv) {
  int bx = blockIdx.x;
  if (bx >= H_ * T_) {
    int i = (bx - H_ * T_) * 128 + threadIdx.x;
    if (i < QKV_)
      bqkv[i] = (i < 512) ? bq[i] : ((i < 1024) ? bk[i - 512] : bv[i - 1024]);
    return;
  }
  int h = bx / T_, t = bx % T_;
  int tr = t / 19, tc = t % 19;
  const float* rh = rpb + h * TABLE_;
  float* br = bias + ((size_t)h * T_ + t) * BSTR_;
  for (int s = threadIdx.x; s < BSTR_; s += blockDim.x) {
    float v = 0.f;
    if (s < T_) {
      int sr = s / 19, sc = s % 19;
      v = rh[(tr - sr + 18) * SPAN_ + (tc - sc + 18)];
    }
    br[s] = v;
  }
}

// ---------------- LayerNorm -> single fp16 ----------------
__global__ __launch_bounds__(128) void ln_h(
    const float* __restrict__ x, const float* __restrict__ g,
    const float* __restrict__ b, __half* __restrict__ y) {
  size_t row = blockIdx.x;
  const float4* xr = (const float4*)(x + row * C_);
  float4 v = xr[threadIdx.x];
  float s  = v.x + v.y + v.z + v.w;
  float s2 = fmaf(v.x, v.x, fmaf(v.y, v.y, fmaf(v.z, v.z, v.w * v.w)));
  #pragma unroll
  for (int o = 16; o; o >>= 1) {
    s  += __shfl_xor_sync(0xffffffffu, s, o);
    s2 += __shfl_xor_sync(0xffffffffu, s2, o);
  }
  __shared__ float sh[8];
  int w = threadIdx.x >> 5, ln = threadIdx.x & 31;
  if (ln == 0) { sh[w] = s; sh[4 + w] = s2; }
  __syncthreads();
  s  = sh[0] + sh[1] + sh[2] + sh[3];
  s2 = sh[4] + sh[5] + sh[6] + sh[7];
  float mu  = s * (1.0f / C_);
  float var = s2 * (1.0f / C_) - mu * mu;
  float rs  = rsqrtf(var + 1e-6f);
  float4 gg = ((const float4*)g)[threadIdx.x];
  float4 bb = ((const float4*)b)[threadIdx.x];
  uint32_t h01 = pk2h((v.x - mu) * rs * gg.x + bb.x, (v.y - mu) * rs * gg.y + bb.y);
  uint32_t h23 = pk2h((v.z - mu) * rs * gg.z + bb.z, (v.w - mu) * rs * gg.w + bb.w);
  *(uint2*)(y + row * C_ + threadIdx.x * 4) = make_uint2(h01, h23);
}

// ---------------- mma.sync GEMM: 1-term fp16, BK=64, warp-staggered k16 ----------------
// D[M,N] = A[M,K] @ B[N,K]^T, fp32 accum.
// smem/stage: A 128x64h (16K) | B 128x64h (16K) = 32KB; 2 stages = 64KB.
// Row = 8 x 16B chunks; swizzle chunk c at row r -> c ^ (r & 7).
// Warp-group (wid>>2) rotates its k16 order by 2 so SMSP-sharing warps are in
// opposite ldsm/mma phases; prefetch split A-then-B to spread the store burst.
#define ST_SZ 32768
#define GMMA_SMEM (2 * ST_SZ)

template<int EPI>  // 1:+bias+res->Cf  2:gelu(+bias)->Ch  3:+bias->Ch
__global__ __launch_bounds__(256, 2) void gemm_mma(
    const __half* __restrict__ Aw, const __half* __restrict__ Bw,
    const float* __restrict__ bias, const float* __restrict__ res,
    float* __restrict__ Cf, __half* __restrict__ Ch, int N, int K) {
  extern __shared__ char smc[];
  uint32_t sb = smem_u32(smc);
  int tid = threadIdx.x, lane = tid & 31, wid = tid >> 5;
  int wm = wid & 3, wn = wid >> 2;
  size_t row0 = (size_t)blockIdx.y * 128;
  int col0 = blockIdx.x * 128;
  const int nk = K >> 6;
  const int krot = (wid >> 2) << 1;   // 0 or 2: stagger within SMSP

  float acc[2][8][4];
  #pragma unroll
  for (int i = 0; i < 2; i++)
    #pragma unroll
    for (int j = 0; j < 8; j++)
      #pragma unroll
      for (int q = 0; q < 4; q++) acc[i][j][q] = 0.f;

  #define PREF_HALF(kc, stg, tl) do {                                          \
    const __half* src_ = (tl) ? Bw : Aw;                                       \
    size_t rb_ = (tl) ? (size_t)col0 : row0;                                   \
    _Pragma("unroll")                                                          \
    for (int i_ = 0; i_ < 4; i_++) {                                           \
      int idx_ = tid + i_ * 256;                                               \
      int r_ = idx_ >> 3, c_ = idx_ & 7;                                       \
      uint32_t sa_ = sb + (stg) * ST_SZ + (tl) * 16384 + r_ * 128 +            \
                     ((c_ ^ (r_ & 7)) << 4);                                   \
      const char* ga_ = (const char*)(src_ +                                   \
                        (rb_ + r_) * (size_t)K + (kc) * 64) + c_ * 16;         \
      cpa16(sa_, ga_);                                                         \
    }                                                                          \
    CP_COMMIT();                                                               \
  } while (0)

  PREF_HALF(0, 0, 0);
  PREF_HALF(0, 0, 1);

  for (int kc = 0; kc < nk; kc++) {
    int s = kc & 1;
    cp_wait<0>();            // stage s fully landed (all outstanding groups)
    __syncthreads();         // visibility + readers done with stage s^1
    bool more = (kc + 1 < nk);
    if (more) PREF_HALF(kc + 1, s ^ 1, 0);   // A-half right away
    uint32_t tb = sb + s * ST_SZ;
    #pragma unroll
    for (int kk = 0; kk < 4; kk++) {
      int k16 = (kk + krot) & 3;
      int c0 = k16 * 2;
      uint32_t af[2][4], bfr[4][4];
      #pragma unroll
      for (int fi = 0; fi < 2; fi++) {
        int lr = wm * 32 + fi * 16 + (lane & 15);
        int ch = c0 + (lane >> 4);
        uint32_t ad = tb + lr * 128 + ((ch ^ (lr & 7)) << 4);
        ldsm4(af[fi], ad);
      }
      #pragma unroll
      for (int p = 0; p < 4; p++) {
        int nr = wn * 64 + p * 16 + ((lane >> 4) << 3) + (lane & 7);
        int ch = c0 + ((lane >> 3) & 1);
        uint32_t ad = tb + 16384 + nr * 128 + ((ch ^ (nr & 7)) << 4);
        ldsm4(bfr[p], ad);
      }
      #pragma unroll
      for (int fi = 0; fi < 2; fi++)
        #pragma unroll
        for (int j = 0; j < 8; j++)
          mma16816(acc[fi][j], af[fi], bfr[j >> 1][(j & 1) * 2], bfr[j >> 1][(j & 1) * 2 + 1]);
      if (kk == 0 && more) PREF_HALF(kc + 1, s ^ 1, 1);   // B-half mid-chunk
    }
  }

  // ---- epilogue ----
  int rr = lane >> 2, ce = (lane & 3) * 2;
  #pragma unroll
  for (int fi = 0; fi < 2; fi++) {
    size_t gr0 = row0 + wm * 32 + fi * 16 + rr;
    #pragma unroll
    for (int j = 0; j < 8; j++) {
      int gc = col0 + wn * 64 + j * 8 + ce;
      float2 bv = *(const float2*)(bias + gc);
      float o0 = acc[fi][j][0] + bv.x, o1 = acc[fi][j][1] + bv.y;
      float o2 = acc[fi][j][2] + bv.x, o3 = acc[fi][j][3] + bv.y;
      size_t off0 = gr0 * (size_t)N + gc;
      size_t off1 = off0 + 8 * (size_t)N;
      if (EPI == 1) {
        float2 r0 = *(const float2*)(res + off0);
        float2 r1 = *(const float2*)(res + off1);
        o0 += r0.x; o1 += r0.y; o2 += r1.x; o3 += r1.y;
        *(float2*)(Cf + off0) = make_float2(o0, o1);
        *(float2*)(Cf + off1) = make_float2(o2, o3);
      } else {
        if (EPI == 2) { o0 = gelu_f(o0); o1 = gelu_f(o1); o2 = gelu_f(o2); o3 = gelu_f(o3); }
        *(uint32_t*)(Ch + off0) = pk2h(o0, o1);
        *(uint32_t*)(Ch + off1) = pk2h(o2, o3);
      }
    }
  }
}

// ---------------- tensor-core flash attention (fp16 QKV, 2-term P) ----------------
#define AT_STG_OFF 16384
#define AT_STG_SZ  16384
#define AT_OSM_OFF 0
#define AT_LRED_OFF 49152
#define AT_LINV_OFF 50176
#define AT_SMEM    50688

__global__ __launch_bounds__(256, 1) void attn_mma(
    const __half* __restrict__ qkv, const float* __restrict__ Bt,
    __half* __restrict__ cx) {
  extern __shared__ char smc[];
  uint32_t sb = smem_u32(smc);
  int tid = threadIdx.x, lane = tid & 31, wid = tid >> 5;
  int wm = wid & 3, wn = wid >> 2;
  int bh = blockIdx.y, b = bh >> 3, h = bh & 7;
  int t0 = blockIdx.x * 128;
  const size_t qbase = (size_t)b * T_ * QKV_ + h * DH_;
  const __half* Qf = qkv + qbase;
  const __half* Kf = Qf + 512;
  const __half* Vf = Qf + 1024;
  const size_t obase = (size_t)b * T_ * C_ + h * DH_;

  #pragma unroll
  for (int i = 0; i < 4; i++) {
    int idx = tid + i * 256;
    int r = idx >> 3, c = idx & 7;
    int t = t0 + r;
    bool v = t < T_;
    int tc = v ? t : 0;
    uint32_t sa = sb + r * 128 + ((c ^ (r & 7)) << 4);
    cpa16z(sa, (const char*)(Qf + (size_t)tc * QKV_ + c * 8), v);
  }

  #define PREF_KV(sc_, stg_) do {                                              \
    const __half* srcs_[2] = { Kf, Vf };                                       \
    _Pragma("unroll")                                                          \
    for (int tl_ = 0; tl_ < 2; tl_++) {                                        \
      _Pragma("unroll")                                                        \
      for (int i_ = 0; i_ < 2; i_++) {                                         \
        int idx_ = tid + i_ * 256;                                             \
        int r_ = idx_ >> 3, c_ = idx_ & 7;                                     \
        int s_ = (sc_) * 64 + r_;                                              \
        bool v_ = s_ < T_;                                                     \
        int scl_ = v_ ? s_ : 0;                                                \
        uint32_t sa_ = sb + AT_STG_OFF + (stg_) * AT_STG_SZ + tl_ * 8192 +     \
                       r_ * 128 + ((c_ ^ (r_ & 7)) << 4);                      \
        cpa16z(sa_, (const char*)(srcs_[tl_] + (size_t)scl_ * QKV_ + c_ * 8), v_); \
      }                                                                        \
    }                                                                          \
    CP_COMMIT();                                                               \
  } while (0)

  PREF_KV(0, 0);        // group 0 = Q + KV chunk 0

  float oacc[2][8][4];
  #pragma unroll
  for (int i = 0; i < 2; i++)
    #pragma unroll
    for (int j = 0; j < 8; j++)
      #pragma unroll
      for (int q = 0; q < 4; q++) oacc[i][j][q] = 0.f;
  float lsum[2][2] = {{0.f, 0.f}, {0.f, 0.f}};

  for (int sc = 0; sc < 6; sc++) {
    int s0 = sc * 64;
    cp_wait<0>();        // stage sc landed
    __syncthreads();     // visibility + readers done with stage sc^1
    if (sc < 5) PREF_KV(sc + 1, (sc + 1) & 1);
    uint32_t stg = sb + AT_STG_OFF + (sc & 1) * AT_STG_SZ;

    float2 bfrag[2][4][2];
    {
      int rb0 = t0 + wm * 32 + (lane >> 2);
      #pragma unroll
      for (int fi = 0; fi < 2; fi++) {
        int ra = rb0 + fi * 16, rb = rb0 + fi * 16 + 8;
        int rca = (ra < T_) ? ra : 0;
        int rcb = (rb < T_) ? rb : 0;
        const float* bra = Bt + ((size_t)h * T_ + rca) * BSTR_;
        const float* brb = Bt + ((size_t)h * T_ + rcb) * BSTR_;
        #pragma unroll
        for (int j = 0; j < 4; j++) {
          int cb = s0 + wn * 32 + j * 8 + (lane & 3) * 2;
          bfrag[fi][j][0] = *(const float2*)(bra + cb);
          bfrag[fi][j][1] = *(const float2*)(brb + cb);
        }
      }
    }

    // ---- S = Q K^T (1-term) ----
    float sacc[2][4][4];
    #pragma unroll
    for (int i = 0; i < 2; i++)
      #pragma unroll
      for (int j = 0; j < 4; j++)
        #pragma unroll
        for (int q = 0; q < 4; q++) sacc[i][j][q] = 0.f;

    #pragma unroll
    for (int d16 = 0; d16 < 4; d16++) {
      uint32_t qf_[2][4], kf_[2][4];
      #pragma unroll
      for (int fi = 0; fi < 2; fi++) {
        int lr = wm * 32 + fi * 16 + (lane & 15);
        int ch = d16 * 2 + (lane >> 4);
        uint32_t ad = sb + lr * 128 + ((ch ^ (lr & 7)) << 4);
        ldsm4(qf_[fi], ad);
      }
      #pragma unroll
      for (int p = 0; p < 2; p++) {
        int sr = wn * 32 + p * 16 + ((lane >> 4) << 3) + (lane & 7);
        int ch = d16 * 2 + ((lane >> 3) & 1);
        uint32_t ad = stg + sr * 128 + ((ch ^ (sr & 7)) << 4);
        ldsm4(kf_[p], ad);
      }
      #pragma unroll
      for (int fi = 0; fi < 2; fi++)
        #pragma unroll
        for (int j = 0; j < 4; j++) {
          int p = j >> 1, hf = (j & 1) * 2;
          mma16816(sacc[fi][j], qf_[fi], kf_[p][hf], kf_[p][hf + 1]);
        }
    }

    // ---- softmax (exp, no max) + pack P into fp16 hi/lo fragments ----
    uint32_t pah[2][2][4], pal[2][2][4];
    #pragma unroll
    for (int fi = 0; fi < 2; fi++) {
      #pragma unroll
      for (int j = 0; j < 4; j++) {
        int cb = s0 + wn * 32 + j * 8 + (lane & 3) * 2;
        bool v0 = cb < T_, v1 = (cb + 1) < T_;
        float p0 = v0 ? __expf(fmaf(sacc[fi][j][0], 0.125f, bfrag[fi][j][0].x)) : 0.f;
        float p1 = v1 ? __expf(fmaf(sacc[fi][j][1], 0.125f, bfrag[fi][j][0].y)) : 0.f;
        float p2 = v0 ? __expf(fmaf(sacc[fi][j][2], 0.125f, bfrag[fi][j][1].x)) : 0.f;
        float p3 = v1 ? __expf(fmaf(sacc[fi][j][3], 0.125f, bfrag[fi][j][1].y)) : 0.f;
        lsum[fi][0] += p0 + p1;
        lsum[fi][1] += p2 + p3;
        int kk = j >> 1, sl = (j & 1) * 2;
        pksplit(p0, p1, pah[fi][kk][sl],     pal[fi][kk][sl]);
        pksplit(p2, p3, pah[fi][kk][sl + 1], pal[fi][kk][sl + 1]);
      }
    }

    // ---- O += (Ph+Pl) V (2-term), V via ldmatrix.trans ----
    #pragma unroll
    for (int kk = 0; kk < 2; kk++) {
      uint32_t vf_[4][4];
      #pragma unroll
      for (int dg = 0; dg < 4; dg++) {
        int sr = wn * 32 + kk * 16 + ((lane >> 3) & 1) * 8 + (lane & 7);
        int ch = dg * 2 + (lane >> 4);
        uint32_t ad = stg + 8192 + sr * 128 + ((ch ^ (sr & 7)) << 4);
        ldsm4t(vf_[dg], ad);
      }
      #pragma unroll
      for (int fi = 0; fi < 2; fi++)
        #pragma unroll
        for (int n = 0; n < 8; n++) {
          int dg = n >> 1, hf = (n & 1) * 2;
          mma16816(oacc[fi][n], pah[fi][kk], vf_[dg][hf], vf_[dg][hf + 1]);
          mma16816(oacc[fi][n], pal[fi][kk], vf_[dg][hf], vf_[dg][hf + 1]);
        }
    }
  }

  // ---- epilogue: reduce l, sum O partials via smem (reusing Q/stage region) ----
  #pragma unroll
  for (int fi = 0; fi < 2; fi++)
    #pragma unroll
    for (int hh = 0; hh < 2; hh++) {
      float v = lsum[fi][hh];
      v += __shfl_xor_sync(0xffffffffu, v, 1);
      v += __shfl_xor_sync(0xffffffffu, v, 2);
      lsum[fi][hh] = v;
    }
  float* lred = (float*)(smc + AT_LRED_OFF);
  float* linv = (float*)(smc + AT_LINV_OFF);
  float* osm  = (float*)(smc + AT_OSM_OFF);
  if ((lane & 3) == 0) {
    #pragma unroll
    for (int fi = 0; fi < 2; fi++)
      #pragma unroll
      for (int hh = 0; hh < 2; hh++) {
        int r = wm * 32 + fi * 16 + (lane >> 2) + hh * 8;
        lred[r * 2 + wn] = lsum[fi][hh];
      }
  }
  __syncthreads();
  if (tid < 128) linv[tid] = 1.0f / (lred[tid * 2] + lred[tid * 2 + 1]);
  if (wn == 0) {
    #pragma unroll
    for (int fi = 0; fi < 2; fi++) {
      int r0 = wm * 32 + fi * 16 + (lane >> 2);
      #pragma unroll
      for (int n = 0; n < 8; n++) {
        int c = n * 8 + (lane & 3) * 2;
        osm[r0 * 66 + c]       = oacc[fi][n][0];
        osm[r0 * 66 + c + 1]   = oacc[fi][n][1];
        osm[(r0 + 8) * 66 + c]     = oacc[fi][n][2];
        osm[(r0 + 8) * 66 + c + 1] = oacc[fi][n][3];
      }
    }
  }
  __syncthreads();
  if (wn == 1) {
    #pragma unroll
    for (int fi = 0; fi < 2; fi++) {
      int r0 = wm * 32 + fi * 16 + (lane >> 2);
      #pragma unroll
      for (int n = 0; n < 8; n++) {
        int c = n * 8 + (lane & 3) * 2;
        osm[r0 * 66 + c]       += oacc[fi][n][0];
        osm[r0 * 66 + c + 1]   += oacc[fi][n][1];
        osm[(r0 + 8) * 66 + c]     += oacc[fi][n][2];
        osm[(r0 + 8) * 66 + c + 1] += oacc[fi][n][3];
      }
    }
  }
  __syncthreads();
  #pragma unroll
  for (int i = 0; i < 8; i++) {
    int u = tid + i * 256;
    int r = u >> 4, c4 = (u & 15) * 4;
    int t = t0 + r;
    if (t < T_) {
      float iv = linv[r];
      uint32_t h01 = pk2h(osm[r * 66 + c4]     * iv, osm[r * 66 + c4 + 1] * iv);
      uint32_t h23 = pk2h(osm[r * 66 + c4 + 2] * iv, osm[r * 66 + c4 + 3] * iv);
      *(uint2*)(cx + obase + (size_t)t * C_ + c4) = make_uint2(h01, h23);
    }
  }
}

// ---------------- launch ----------------
extern "C" void kernel_launch(void* const* d_in, const int* in_sizes, int n_in,
                              void* d_out, int out_size) {
  const float* x    = (const float*)d_in[0];
  const float* ln1s = (const float*)d_in[1];
  const float* ln1b = (const float*)d_in[2];
  const float* Wq   = (const float*)d_in[3];
  const float* bq   = (const float*)d_in[4];
  const float* Wk   = (const float*)d_in[5];
  const float* bk   = (const float*)d_in[6];
  const float* Wv   = (const float*)d_in[7];
  const float* bv   = (const float*)d_in[8];
  const float* Wo   = (const float*)d_in[9];
  const float* bo   = (const float*)d_in[10];
  const float* rpb  = (const float*)d_in[11];
  const float* ln2s = (const float*)d_in[12];
  const float* ln2b = (const float*)d_in[13];
  const float* W1   = (const float*)d_in[14];
  const float* b1   = (const float*)d_in[15];
  const float* W2   = (const float*)d_in[16];
  const float* b2   = (const float*)d_in[17];
  float* out = (float*)d_out;

  __half *y, *qkv, *cx, *hi, *wp;
  float *gX1, *gBIAS, *gBQKV;
  cudaGetSymbolAddress((void**)&y,     g_Y);
  cudaGetSymbolAddress((void**)&qkv,   g_QKV);
  cudaGetSymbolAddress((void**)&cx,    g_CX);
  cudaGetSymbolAddress((void**)&gX1,   g_X1);
  cudaGetSymbolAddress((void**)&hi,    g_HI);
  cudaGetSymbolAddress((void**)&gBIAS, g_BIAS);
  cudaGetSymbolAddress((void**)&gBQKV, g_BQKV);
  cudaGetSymbolAddress((void**)&wp,    g_W);

  cudaFuncSetAttribute((const void*)attn_mma,
                       cudaFuncAttributeMaxDynamicSharedMemorySize, AT_SMEM);
  cudaFuncSetAttribute((const void*)gemm_mma<1>,
                       cudaFuncAttributeMaxDynamicSharedMemorySize, GMMA_SMEM);
  cudaFuncSetAttribute((const void*)gemm_mma<2>,
                       cudaFuncAttributeMaxDynamicSharedMemorySize, GMMA_SMEM);
  cudaFuncSetAttribute((const void*)gemm_mma<3>,
                       cudaFuncAttributeMaxDynamicSharedMemorySize, GMMA_SMEM);

  // exactly 3 setup launches so QKV GEMM stays on the profiler capture slot
  wprep_all<<<dim3(64, 64, 6), 256>>>(Wq, Wk, Wv, Wo, W1, W2, wp);         // 1
  setup_bias<<<H_ * T_ + 12, 128>>>(rpb, gBIAS, bq, bk, bv, gBQKV);        // 2
  ln_h<<<M_, 128>>>(x, ln1s, ln1b, y);                                     // 3

  // fused QKV projection -> packed [M,1536] fp16                          // 4
  dim3 gq(QKV_ / 128, M_ / 128);
  gemm_mma<3><<<gq, 256, GMMA_SMEM>>>(y, wp + WOFF_Q, gBQKV,
                                      nullptr, nullptr, qkv, QKV_, C_);
  // attention (tensor pipe)
  dim3 ga(3, B_ * H_);
  attn_mma<<<ga, 256, AT_SMEM>>>(qkv, gBIAS, cx);
  // output projection + residual
  dim3 g1(C_ / 128, M_ / 128);
  gemm_mma<1><<<g1, 256, GMMA_SMEM>>>(cx, wp + WOFF_O, bo,
                                      x, gX1, nullptr, C_, C_);
  // LN2 -> fp16
  ln_h<<<M_, 128>>>(gX1, ln2s, ln2b, y);
  // MLP up + gelu -> fp16
  dim3 g2(MLP_ / 128, M_ / 128);
  gemm_mma<2><<<g2, 256, GMMA_SMEM>>>(y, wp + WOFF_1, b1,
                                      nullptr, nullptr, hi, MLP_, C_);
  // MLP down + residual -> out
  gemm_mma<1><<<g1, 256, GMMA_SMEM>>>(hi, wp + WOFF_2, b2,
                                      gX1, out, nullptr, C_, MLP_);
}

// round 17
// speedup vs baseline: 1.0619x; 1.0619x over previous
#include <cuda_runtime.h>
#include <cuda_fp16.h>
#include <cstdint>
#include <cstddef>

// ---------------- problem constants ----------------
#define B_   256
#define T_   361
#define C_   512
#define H_   8
#define DH_  64
#define MLP_ 2048
#define M_   (B_ * T_)          // 92416 = 722*128
#define SPAN_ 37
#define TABLE_ 1369
#define BSTR_ 384               // padded bias row stride
#define QKV_ 1536               // packed QKV row stride

// ---------------- PTX helpers (baseline features only) ----------------
__device__ __forceinline__ uint32_t smem_u32(const void* p) {
  uint32_t a;
  asm("{ .reg .u64 t; cvta.to.shared.u64 t, %1; cvt.u32.u64 %0, t; }" : "=r"(a) : "l"(p));
  return a;
}
__device__ __forceinline__ void cpa16(uint32_t s, const void* g) {
  asm volatile("cp.async.cg.shared.global [%0], [%1], 16;" :: "r"(s), "l"(g));
}
__device__ __forceinline__ void cpa16z(uint32_t s, const void* g, bool v) {
  int sz = v ? 16 : 0;
  asm volatile("cp.async.cg.shared.global [%0], [%1], 16, %2;" :: "r"(s), "l"(g), "r"(sz));
}
#define CP_COMMIT() asm volatile("cp.async.commit_group;" ::: "memory")
template<int Nw> __device__ __forceinline__ void cp_wait() {
  asm volatile("cp.async.wait_group %0;" :: "n"(Nw) : "memory");
}
__device__ __forceinline__ void ldsm4(uint32_t* r, uint32_t a) {
  asm volatile("ldmatrix.sync.aligned.m8n8.x4.shared.b16 {%0,%1,%2,%3}, [%4];"
               : "=r"(r[0]), "=r"(r[1]), "=r"(r[2]), "=r"(r[3]) : "r"(a));
}
__device__ __forceinline__ void ldsm4t(uint32_t* r, uint32_t a) {
  asm volatile("ldmatrix.sync.aligned.m8n8.x4.trans.shared.b16 {%0,%1,%2,%3}, [%4];"
               : "=r"(r[0]), "=r"(r[1]), "=r"(r[2]), "=r"(r[3]) : "r"(a));
}
__device__ __forceinline__ void mma16816(float* c, const uint32_t* a,
                                         uint32_t b0, uint32_t b1) {
  asm volatile(
      "mma.sync.aligned.m16n8k16.row.col.f32.f16.f16.f32 "
      "{%0,%1,%2,%3}, {%4,%5,%6,%7}, {%8,%9}, {%0,%1,%2,%3};"
      : "+f"(c[0]), "+f"(c[1]), "+f"(c[2]), "+f"(c[3])
      : "r"(a[0]), "r"(a[1]), "r"(a[2]), "r"(a[3]), "r"(b0), "r"(b1));
}

// ---------------- scratch (static device globals) ----------------
__device__ __half g_Y   [(size_t)M_ * C_];
__device__ __half g_QKV [(size_t)M_ * QKV_ + 64 * QKV_];
__device__ __half g_CX  [(size_t)M_ * C_];
__device__ float  g_X1  [(size_t)M_ * C_];
__device__ __half g_HI  [(size_t)M_ * MLP_];
__device__ float  g_BIAS[(size_t)H_ * T_ * BSTR_ + 16];
__device__ float  g_BQKV[QKV_];
#define WOFF_Q  0
#define WOFF_K  (512 * 512)
#define WOFF_V  (2 * 512 * 512)
#define WOFF_O  (3 * 512 * 512)
#define WOFF_1  (4 * 512 * 512)
#define WOFF_2  (4 * 512 * 512 + 2048 * 512)
#define WTOT    (4 * 512 * 512 + 2 * 2048 * 512)
__device__ __half g_W[WTOT];           // single-fp16 transposed weights [N,K]

// ---------------- helpers ----------------
__device__ __forceinline__ uint32_t pk2h(float a, float b) {
  __half2 h = __floats2half2_rn(a, b);
  return *(uint32_t*)&h;
}
__device__ __forceinline__ float gelu_f(float x) {
  float x3 = x * x * x;
  float t = tanhf(0.7978845608028654f * fmaf(0.044715f, x3, x));
  return 0.5f * x * (1.0f + t);
}

// ---------------- weight prep (all 6 weights, one launch, single fp16) ----------------
__global__ __launch_bounds__(256) void wprep_all(
    const float* __restrict__ Wq, const float* __restrict__ Wk,
    const float* __restrict__ Wv, const float* __restrict__ Wo,
    const float* __restrict__ W1, const float* __restrict__ W2,
    __half* __restrict__ wout) {
  int z = blockIdx.z;
  const float* W; int K, N; size_t off;
  switch (z) {
    case 0: W = Wq; K = 512;  N = 512;  off = WOFF_Q; break;
    case 1: W = Wk; K = 512;  N = 512;  off = WOFF_K; break;
    case 2: W = Wv; K = 512;  N = 512;  off = WOFF_V; break;
    case 3: W = Wo; K = 512;  N = 512;  off = WOFF_O; break;
    case 4: W = W1; K = 512;  N = 2048; off = WOFF_1; break;
    default:W = W2; K = 2048; N = 512;  off = WOFF_2; break;
  }
  int n0 = blockIdx.x * 32, k0 = blockIdx.y * 32;
  if (n0 >= N || k0 >= K) return;
  __half* wo = wout + off;
  __shared__ float ts[32][33];
  int tr = threadIdx.x >> 5, tc = threadIdx.x & 31;
  #pragma unroll
  for (int i = 0; i < 4; i++) {
    int r = tr + i * 8;
    ts[r][tc] = W[(size_t)(k0 + r) * N + n0 + tc];
  }
  __syncthreads();
  #pragma unroll
  for (int i = 0; i < 4; i++) {
    int r = tr + i * 8;
    wo[(size_t)(n0 + r) * K + k0 + tc] = __float2half_rn(ts[tc][r]);
  }
}

// ---------------- bias expansion + QKV bias concat ----------------
__global__ void setup_bias(const float* __restrict__ rpb, float* __restrict__ bias,
                           const float* __restrict__ bq, const float* __restrict__ bk,
                           const float* __restrict__ bv, float* __restrict__ bqkv) {
  int bx = blockIdx.x;
  if (bx >= H_ * T_) {
    int i = (bx - H_ * T_) * 128 + threadIdx.x;
    if (i < QKV_)
      bqkv[i] = (i < 512) ? bq[i] : ((i < 1024) ? bk[i - 512] : bv[i - 1024]);
    return;
  }
  int h = bx / T_, t = bx % T_;
  int tr = t / 19, tc = t % 19;
  const float* rh = rpb + h * TABLE_;
  float* br = bias + ((size_t)h * T_ + t) * BSTR_;
  for (int s = threadIdx.x; s < BSTR_; s += blockDim.x) {
    float v = 0.f;
    if (s < T_) {
      int sr = s / 19, sc = s % 19;
      v = rh[(tr - sr + 18) * SPAN_ + (tc - sc + 18)];
    }
    br[s] = v;
  }
}

// ---------------- LayerNorm -> single fp16 ----------------
__global__ __launch_bounds__(128) void ln_h(
    const float* __restrict__ x, const float* __restrict__ g,
    const float* __restrict__ b, __half* __restrict__ y) {
  size_t row = blockIdx.x;
  const float4* xr = (const float4*)(x + row * C_);
  float4 v = xr[threadIdx.x];
  float s  = v.x + v.y + v.z + v.w;
  float s2 = fmaf(v.x, v.x, fmaf(v.y, v.y, fmaf(v.z, v.z, v.w * v.w)));
  #pragma unroll
  for (int o = 16; o; o >>= 1) {
    s  += __shfl_xor_sync(0xffffffffu, s, o);
    s2 += __shfl_xor_sync(0xffffffffu, s2, o);
  }
  __shared__ float sh[8];
  int w = threadIdx.x >> 5, ln = threadIdx.x & 31;
  if (ln == 0) { sh[w] = s; sh[4 + w] = s2; }
  __syncthreads();
  s  = sh[0] + sh[1] + sh[2] + sh[3];
  s2 = sh[4] + sh[5] + sh[6] + sh[7];
  float mu  = s * (1.0f / C_);
  float var = s2 * (1.0f / C_) - mu * mu;
  float rs  = rsqrtf(var + 1e-6f);
  float4 gg = ((const float4*)g)[threadIdx.x];
  float4 bb = ((const float4*)b)[threadIdx.x];
  uint32_t h01 = pk2h((v.x - mu) * rs * gg.x + bb.x, (v.y - mu) * rs * gg.y + bb.y);
  uint32_t h23 = pk2h((v.z - mu) * rs * gg.z + bb.z, (v.w - mu) * rs * gg.w + bb.w);
  *(uint2*)(y + row * C_ + threadIdx.x * 4) = make_uint2(h01, h23);
}

// ---------------- mma.sync GEMM: 1-term fp16, BK=64 (proven R15 form) ----------------
// D[M,N] = A[M,K] @ B[N,K]^T, fp32 accum.
// smem/stage: A 128x64h (16K) | B 128x64h (16K) = 32KB; 2 stages = 64KB.
// Row = 8 x 16B chunks; swizzle chunk c at row r -> c ^ (r & 7).
#define ST_SZ 32768
#define GMMA_SMEM (2 * ST_SZ)

template<int EPI>  // 1:+bias+res->Cf  2:gelu(+bias)->Ch  3:+bias->Ch
__global__ __launch_bounds__(256, 2) void gemm_mma(
    const __half* __restrict__ Aw, const __half* __restrict__ Bw,
    const float* __restrict__ bias, const float* __restrict__ res,
    float* __restrict__ Cf, __half* __restrict__ Ch, int N, int K) {
  extern __shared__ char smc[];
  uint32_t sb = smem_u32(smc);
  int tid = threadIdx.x, lane = tid & 31, wid = tid >> 5;
  int wm = wid & 3, wn = wid >> 2;
  size_t row0 = (size_t)blockIdx.y * 128;
  int col0 = blockIdx.x * 128;
  const int nk = K >> 6;

  float acc[2][8][4];
  #pragma unroll
  for (int i = 0; i < 2; i++)
    #pragma unroll
    for (int j = 0; j < 8; j++)
      #pragma unroll
      for (int q = 0; q < 4; q++) acc[i][j][q] = 0.f;

  #define PREFETCH(kc, stg) do {                                               \
    const __half* srcs_[2] = { Aw, Bw };                                       \
    _Pragma("unroll")                                                          \
    for (int tl_ = 0; tl_ < 2; tl_++) {                                        \
      size_t rb_ = (tl_ == 0) ? row0 : (size_t)col0;                           \
      _Pragma("unroll")                                                        \
      for (int i_ = 0; i_ < 4; i_++) {                                         \
        int idx_ = tid + i_ * 256;                                             \
        int r_ = idx_ >> 3, c_ = idx_ & 7;                                     \
        uint32_t sa_ = sb + (stg) * ST_SZ + tl_ * 16384 + r_ * 128 +           \
                       ((c_ ^ (r_ & 7)) << 4);                                 \
        const char* ga_ = (const char*)(srcs_[tl_] +                           \
                          (rb_ + r_) * (size_t)K + (kc) * 64) + c_ * 16;       \
        cpa16(sa_, ga_);                                                       \
      }                                                                        \
    }                                                                          \
    CP_COMMIT();                                                               \
  } while (0)

  PREFETCH(0, 0);

  for (int kc = 0; kc < nk; kc++) {
    int s = kc & 1;
    cp_wait<0>();            // stage s landed (only outstanding group)
    __syncthreads();         // visibility + readers done with stage s^1
    if (kc + 1 < nk) PREFETCH(kc + 1, s ^ 1);
    uint32_t tb = sb + s * ST_SZ;
    #pragma unroll
    for (int k16 = 0; k16 < 4; k16++) {
      int c0 = k16 * 2;
      uint32_t af[2][4], bfr[4][4];
      #pragma unroll
      for (int fi = 0; fi < 2; fi++) {
        int lr = wm * 32 + fi * 16 + (lane & 15);
        int ch = c0 + (lane >> 4);
        uint32_t ad = tb + lr * 128 + ((ch ^ (lr & 7)) << 4);
        ldsm4(af[fi], ad);
      }
      #pragma unroll
      for (int p = 0; p < 4; p++) {
        int nr = wn * 64 + p * 16 + ((lane >> 4) << 3) + (lane & 7);
        int ch = c0 + ((lane >> 3) & 1);
        uint32_t ad = tb + 16384 + nr * 128 + ((ch ^ (nr & 7)) << 4);
        ldsm4(bfr[p], ad);
      }
      #pragma unroll
      for (int fi = 0; fi < 2; fi++)
        #pragma unroll
        for (int j = 0; j < 8; j++)
          mma16816(acc[fi][j], af[fi], bfr[j >> 1][(j & 1) * 2], bfr[j >> 1][(j & 1) * 2 + 1]);
    }
  }

  // ---- epilogue ----
  int rr = lane >> 2, ce = (lane & 3) * 2;
  #pragma unroll
  for (int fi = 0; fi < 2; fi++) {
    size_t gr0 = row0 + wm * 32 + fi * 16 + rr;
    #pragma unroll
    for (int j = 0; j < 8; j++) {
      int gc = col0 + wn * 64 + j * 8 + ce;
      float2 bv = *(const float2*)(bias + gc);
      float o0 = acc[fi][j][0] + bv.x, o1 = acc[fi][j][1] + bv.y;
      float o2 = acc[fi][j][2] + bv.x, o3 = acc[fi][j][3] + bv.y;
      size_t off0 = gr0 * (size_t)N + gc;
      size_t off1 = off0 + 8 * (size_t)N;
      if (EPI == 1) {
        float2 r0 = *(const float2*)(res + off0);
        float2 r1 = *(const float2*)(res + off1);
        o0 += r0.x; o1 += r0.y; o2 += r1.x; o3 += r1.y;
        *(float2*)(Cf + off0) = make_float2(o0, o1);
        *(float2*)(Cf + off1) = make_float2(o2, o3);
      } else {
        if (EPI == 2) { o0 = gelu_f(o0); o1 = gelu_f(o1); o2 = gelu_f(o2); o3 = gelu_f(o3); }
        *(uint32_t*)(Ch + off0) = pk2h(o0, o1);
        *(uint32_t*)(Ch + off1) = pk2h(o2, o3);
      }
    }
  }
}

// ---------------- tensor-core flash attention (fp16 QKV, 1-term P, occ 2) ----------------
#define AT_STG_OFF 16384
#define AT_STG_SZ  16384
#define AT_OSM_OFF 0
#define AT_LRED_OFF 49152
#define AT_LINV_OFF 50176
#define AT_SMEM    50688

__global__ __launch_bounds__(256, 2) void attn_mma(
    const __half* __restrict__ qkv, const float* __restrict__ Bt,
    __half* __restrict__ cx) {
  extern __shared__ char smc[];
  uint32_t sb = smem_u32(smc);
  int tid = threadIdx.x, lane = tid & 31, wid = tid >> 5;
  int wm = wid & 3, wn = wid >> 2;
  int bh = blockIdx.y, b = bh >> 3, h = bh & 7;
  int t0 = blockIdx.x * 128;
  const size_t qbase = (size_t)b * T_ * QKV_ + h * DH_;
  const __half* Qf = qkv + qbase;
  const __half* Kf = Qf + 512;
  const __half* Vf = Qf + 1024;
  const size_t obase = (size_t)b * T_ * C_ + h * DH_;

  #pragma unroll
  for (int i = 0; i < 4; i++) {
    int idx = tid + i * 256;
    int r = idx >> 3, c = idx & 7;
    int t = t0 + r;
    bool v = t < T_;
    int tc = v ? t : 0;
    uint32_t sa = sb + r * 128 + ((c ^ (r & 7)) << 4);
    cpa16z(sa, (const char*)(Qf + (size_t)tc * QKV_ + c * 8), v);
  }

  #define PREF_KV(sc_, stg_) do {                                              \
    const __half* srcs_[2] = { Kf, Vf };                                       \
    _Pragma("unroll")                                                          \
    for (int tl_ = 0; tl_ < 2; tl_++) {                                        \
      _Pragma("unroll")                                                        \
      for (int i_ = 0; i_ < 2; i_++) {                                         \
        int idx_ = tid + i_ * 256;                                             \
        int r_ = idx_ >> 3, c_ = idx_ & 7;                                     \
        int s_ = (sc_) * 64 + r_;                                              \
        bool v_ = s_ < T_;                                                     \
        int scl_ = v_ ? s_ : 0;                                                \
        uint32_t sa_ = sb + AT_STG_OFF + (stg_) * AT_STG_SZ + tl_ * 8192 +     \
                       r_ * 128 + ((c_ ^ (r_ & 7)) << 4);                      \
        cpa16z(sa_, (const char*)(srcs_[tl_] + (size_t)scl_ * QKV_ + c_ * 8), v_); \
      }                                                                        \
    }                                                                          \
    CP_COMMIT();                                                               \
  } while (0)

  PREF_KV(0, 0);        // group 0 = Q + KV chunk 0

  float oacc[2][8][4];
  #pragma unroll
  for (int i = 0; i < 2; i++)
    #pragma unroll
    for (int j = 0; j < 8; j++)
      #pragma unroll
      for (int q = 0; q < 4; q++) oacc[i][j][q] = 0.f;
  float lsum[2][2] = {{0.f, 0.f}, {0.f, 0.f}};

  for (int sc = 0; sc < 6; sc++) {
    int s0 = sc * 64;
    cp_wait<0>();        // stage sc landed
    __syncthreads();     // visibility + readers done with stage sc^1
    if (sc < 5) PREF_KV(sc + 1, (sc + 1) & 1);
    uint32_t stg = sb + AT_STG_OFF + (sc & 1) * AT_STG_SZ;

    float2 bfrag[2][4][2];
    {
      int rb0 = t0 + wm * 32 + (lane >> 2);
      #pragma unroll
      for (int fi = 0; fi < 2; fi++) {
        int ra = rb0 + fi * 16, rb = rb0 + fi * 16 + 8;
        int rca = (ra < T_) ? ra : 0;
        int rcb = (rb < T_) ? rb : 0;
        const float* bra = Bt + ((size_t)h * T_ + rca) * BSTR_;
        const float* brb = Bt + ((size_t)h * T_ + rcb) * BSTR_;
        #pragma unroll
        for (int j = 0; j < 4; j++) {
          int cb = s0 + wn * 32 + j * 8 + (lane & 3) * 2;
          bfrag[fi][j][0] = *(const float2*)(bra + cb);
          bfrag[fi][j][1] = *(const float2*)(brb + cb);
        }
      }
    }

    // ---- S = Q K^T (1-term) ----
    float sacc[2][4][4];
    #pragma unroll
    for (int i = 0; i < 2; i++)
      #pragma unroll
      for (int j = 0; j < 4; j++)
        #pragma unroll
        for (int q = 0; q < 4; q++) sacc[i][j][q] = 0.f;

    #pragma unroll
    for (int d16 = 0; d16 < 4; d16++) {
      uint32_t qf_[2][4], kf_[2][4];
      #pragma unroll
      for (int fi = 0; fi < 2; fi++) {
        int lr = wm * 32 + fi * 16 + (lane & 15);
        int ch = d16 * 2 + (lane >> 4);
        uint32_t ad = sb + lr * 128 + ((ch ^ (lr & 7)) << 4);
        ldsm4(qf_[fi], ad);
      }
      #pragma unroll
      for (int p = 0; p < 2; p++) {
        int sr = wn * 32 + p * 16 + ((lane >> 4) << 3) + (lane & 7);
        int ch = d16 * 2 + ((lane >> 3) & 1);
        uint32_t ad = stg + sr * 128 + ((ch ^ (sr & 7)) << 4);
        ldsm4(kf_[p], ad);
      }
      #pragma unroll
      for (int fi = 0; fi < 2; fi++)
        #pragma unroll
        for (int j = 0; j < 4; j++) {
          int p = j >> 1, hf = (j & 1) * 2;
          mma16816(sacc[fi][j], qf_[fi], kf_[p][hf], kf_[p][hf + 1]);
        }
    }

    // ---- softmax (exp, no max) + pack P into single fp16 fragments ----
    uint32_t pah[2][2][4];
    #pragma unroll
    for (int fi = 0; fi < 2; fi++) {
      #pragma unroll
      for (int j = 0; j < 4; j++) {
        int cb = s0 + wn * 32 + j * 8 + (lane & 3) * 2;
        bool v0 = cb < T_, v1 = (cb + 1) < T_;
        float p0 = v0 ? __expf(fmaf(sacc[fi][j][0], 0.125f, bfrag[fi][j][0].x)) : 0.f;
        float p1 = v1 ? __expf(fmaf(sacc[fi][j][1], 0.125f, bfrag[fi][j][0].y)) : 0.f;
        float p2 = v0 ? __expf(fmaf(sacc[fi][j][2], 0.125f, bfrag[fi][j][1].x)) : 0.f;
        float p3 = v1 ? __expf(fmaf(sacc[fi][j][3], 0.125f, bfrag[fi][j][1].y)) : 0.f;
        lsum[fi][0] += p0 + p1;
        lsum[fi][1] += p2 + p3;
        int kk = j >> 1, sl = (j & 1) * 2;
        pah[fi][kk][sl]     = pk2h(p0, p1);
        pah[fi][kk][sl + 1] = pk2h(p2, p3);
      }
    }

    // ---- O += P V (1-term), V via ldmatrix.trans ----
    #pragma unroll
    for (int kk = 0; kk < 2; kk++) {
      uint32_t vf_[4][4];
      #pragma unroll
      for (int dg = 0; dg < 4; dg++) {
        int sr = wn * 32 + kk * 16 + ((lane >> 3) & 1) * 8 + (lane & 7);
        int ch = dg * 2 + (lane >> 4);
        uint32_t ad = stg + 8192 + sr * 128 + ((ch ^ (sr & 7)) << 4);
        ldsm4t(vf_[dg], ad);
      }
      #pragma unroll
      for (int fi = 0; fi < 2; fi++)
        #pragma unroll
        for (int n = 0; n < 8; n++) {
          int dg = n >> 1, hf = (n & 1) * 2;
          mma16816(oacc[fi][n], pah[fi][kk], vf_[dg][hf], vf_[dg][hf + 1]);
        }
    }
  }

  // ---- epilogue: reduce l, sum O partials via smem (reusing Q/stage region) ----
  #pragma unroll
  for (int fi = 0; fi < 2; fi++)
    #pragma unroll
    for (int hh = 0; hh < 2; hh++) {
      float v = lsum[fi][hh];
      v += __shfl_xor_sync(0xffffffffu, v, 1);
      v += __shfl_xor_sync(0xffffffffu, v, 2);
      lsum[fi][hh] = v;
    }
  float* lred = (float*)(smc + AT_LRED_OFF);
  float* linv = (float*)(smc + AT_LINV_OFF);
  float* osm  = (float*)(smc + AT_OSM_OFF);
  if ((lane & 3) == 0) {
    #pragma unroll
    for (int fi = 0; fi < 2; fi++)
      #pragma unroll
      for (int hh = 0; hh < 2; hh++) {
        int r = wm * 32 + fi * 16 + (lane >> 2) + hh * 8;
        lred[r * 2 + wn] = lsum[fi][hh];
      }
  }
  __syncthreads();
  if (tid < 128) linv[tid] = 1.0f / (lred[tid * 2] + lred[tid * 2 + 1]);
  if (wn == 0) {
    #pragma unroll
    for (int fi = 0; fi < 2; fi++) {
      int r0 = wm * 32 + fi * 16 + (lane >> 2);
      #pragma unroll
      for (int n = 0; n < 8; n++) {
        int c = n * 8 + (lane & 3) * 2;
        osm[r0 * 66 + c]       = oacc[fi][n][0];
        osm[r0 * 66 + c + 1]   = oacc[fi][n][1];
        osm[(r0 + 8) * 66 + c]     = oacc[fi][n][2];
        osm[(r0 + 8) * 66 + c + 1] = oacc[fi][n][3];
      }
    }
  }
  __syncthreads();
  if (wn == 1) {
    #pragma unroll
    for (int fi = 0; fi < 2; fi++) {
      int r0 = wm * 32 + fi * 16 + (lane >> 2);
      #pragma unroll
      for (int n = 0; n < 8; n++) {
        int c = n * 8 + (lane & 3) * 2;
        osm[r0 * 66 + c]       += oacc[fi][n][0];
        osm[r0 * 66 + c + 1]   += oacc[fi][n][1];
        osm[(r0 + 8) * 66 + c]     += oacc[fi][n][2];
        osm[(r0 + 8) * 66 + c + 1] += oacc[fi][n][3];
      }
    }
  }
  __syncthreads();
  #pragma unroll
  for (int i = 0; i < 8; i++) {
    int u = tid + i * 256;
    int r = u >> 4, c4 = (u & 15) * 4;
    int t = t0 + r;
    if (t < T_) {
      float iv = linv[r];
      uint32_t h01 = pk2h(osm[r * 66 + c4]     * iv, osm[r * 66 + c4 + 1] * iv);
      uint32_t h23 = pk2h(osm[r * 66 + c4 + 2] * iv, osm[r * 66 + c4 + 3] * iv);
      *(uint2*)(cx + obase + (size_t)t * C_ + c4) = make_uint2(h01, h23);
    }
  }
}

// ---------------- launch ----------------
extern "C" void kernel_launch(void* const* d_in, const int* in_sizes, int n_in,
                              void* d_out, int out_size) {
  const float* x    = (const float*)d_in[0];
  const float* ln1s = (const float*)d_in[1];
  const float* ln1b = (const float*)d_in[2];
  const float* Wq   = (const float*)d_in[3];
  const float* bq   = (const float*)d_in[4];
  const float* Wk   = (const float*)d_in[5];
  const float* bk   = (const float*)d_in[6];
  const float* Wv   = (const float*)d_in[7];
  const float* bv   = (const float*)d_in[8];
  const float* Wo   = (const float*)d_in[9];
  const float* bo   = (const float*)d_in[10];
  const float* rpb  = (const float*)d_in[11];
  const float* ln2s = (const float*)d_in[12];
  const float* ln2b = (const float*)d_in[13];
  const float* W1   = (const float*)d_in[14];
  const float* b1   = (const float*)d_in[15];
  const float* W2   = (const float*)d_in[16];
  const float* b2   = (const float*)d_in[17];
  float* out = (float*)d_out;

  __half *y, *qkv, *cx, *hi, *wp;
  float *gX1, *gBIAS, *gBQKV;
  cudaGetSymbolAddress((void**)&y,     g_Y);
  cudaGetSymbolAddress((void**)&qkv,   g_QKV);
  cudaGetSymbolAddress((void**)&cx,    g_CX);
  cudaGetSymbolAddress((void**)&gX1,   g_X1);
  cudaGetSymbolAddress((void**)&hi,    g_HI);
  cudaGetSymbolAddress((void**)&gBIAS, g_BIAS);
  cudaGetSymbolAddress((void**)&gBQKV, g_BQKV);
  cudaGetSymbolAddress((void**)&wp,    g_W);

  cudaFuncSetAttribute((const void*)attn_mma,
                       cudaFuncAttributeMaxDynamicSharedMemorySize, AT_SMEM);
  cudaFuncSetAttribute((const void*)gemm_mma<1>,
                       cudaFuncAttributeMaxDynamicSharedMemorySize, GMMA_SMEM);
  cudaFuncSetAttribute((const void*)gemm_mma<2>,
                       cudaFuncAttributeMaxDynamicSharedMemorySize, GMMA_SMEM);
  cudaFuncSetAttribute((const void*)gemm_mma<3>,
                       cudaFuncAttributeMaxDynamicSharedMemorySize, GMMA_SMEM);

  // exactly 3 setup launches so QKV GEMM stays on the profiler capture slot
  wprep_all<<<dim3(64, 64, 6), 256>>>(Wq, Wk, Wv, Wo, W1, W2, wp);         // 1
  setup_bias<<<H_ * T_ + 12, 128>>>(rpb, gBIAS, bq, bk, bv, gBQKV);        // 2
  ln_h<<<M_, 128>>>(x, ln1s, ln1b, y);                                     // 3

  // fused QKV projection -> packed [M,1536] fp16                          // 4
  dim3 gq(QKV_ / 128, M_ / 128);
  gemm_mma<3><<<gq, 256, GMMA_SMEM>>>(y, wp + WOFF_Q, gBQKV,
                                      nullptr, nullptr, qkv, QKV_, C_);
  // attention (tensor pipe, occ 2)
  dim3 ga(3, B_ * H_);
  attn_mma<<<ga, 256, AT_SMEM>>>(qkv, gBIAS, cx);
  // output projection + residual
  dim3 g1(C_ / 128, M_ / 128);
  gemm_mma<1><<<g1, 256, GMMA_SMEM>>>(cx, wp + WOFF_O, bo,
                                      x, gX1, nullptr, C_, C_);
  // LN2 -> fp16
  ln_h<<<M_, 128>>>(gX1, ln2s, ln2b, y);
  // MLP up + gelu -> fp16
  dim3 g2(MLP_ / 128, M_ / 128);
  gemm_mma<2><<<g2, 256, GMMA_SMEM>>>(y, wp + WOFF_1, b1,
                                      nullptr, nullptr, hi, MLP_, C_);
  // MLP down + residual -> out
  gemm_mma<1><<<g1, 256, GMMA_SMEM>>>(hi, wp + WOFF_2, b2,
                                      gX1, out, nullptr, C_, MLP_);
}